// round 16
// baseline (speedup 1.0000x reference)
#include <cuda_runtime.h>
#include <cuda_bf16.h>
#include <cuda_fp16.h>
#include <cstdint>

typedef unsigned long long u64;

#define SEQL   512
#define BATCH  32
#define HDIM   1024
#define VOCAB  8192
#define ML     (BATCH*SEQL)              /* 16384 */
#define LOGITS_ELEMS 134217728           /* 32*512*8192 */
#define K2     2048                      /* scan h-exchange rows: [hi|lo] */
#define BK     64
#define KCH    16                        /* HDIM / BK — plain fp16 GEMM */
#define STAGE_BYTES 49152                /* (256+128)*64*2 */
#define NSTAGE 3
#define WROWB   2064                     /* bytes per scan smem row (1032 halfs) */
#define SCAN_SMEM 66048                  /* 32 rows * 2064 B */

// ---------------- scratch (cudaMalloc forbidden) ----------------
__device__ float g_pre[ML*HDIM];                 // 64 MB, [t][b][h]
__device__ float g_hout[ML*HDIM];                // 64 MB (only t=511 used)
__device__ __half g_hx[(size_t)ML*K2];           // 64 MB: scan h-exchange [hi|lo]
__device__ __half g_a1[(size_t)ML*HDIM];         // 32 MB: fp16 A rows (hi only)
__device__ __half g_bo[(size_t)VOCAB*HDIM];      // 16 MB: fp16 W_o (hi only)
__device__ __half g_be[(size_t)HDIM*HDIM];       //  2 MB: fp16 W_e (hi only)
__device__ __half g_h0[BATCH*K2];                // 128 KB: initial hidden [hi|lo]
__device__ int   g_map1[ML];             // row m=t*32+b -> embedding id
__device__ int   g_is64;
__device__ unsigned g_bar4[4*64];        // per-batch-group barrier counters

// ---------------- barrier primitives ----------------
__device__ __forceinline__ void bar_arrive_release(unsigned* p){
    asm volatile("red.release.gpu.global.add.u32 [%0], 1;" :: "l"(p) : "memory");
}
__device__ __forceinline__ unsigned ld_acquire_gpu(const unsigned* p){
    unsigned v;
    asm volatile("ld.acquire.gpu.global.u32 %0, [%1];" : "=r"(v) : "l"(p) : "memory");
    return v;
}

// ---------------- sm80-class tensor primitives (valid on plain sm_103) ----------------
__device__ __forceinline__ unsigned smem_u32(const void* p){
    unsigned a;
    asm("{ .reg .u64 t; cvta.to.shared.u64 t, %1; cvt.u32.u64 %0, t; }" : "=r"(a) : "l"(p));
    return a;
}
__device__ __forceinline__ void ldsm4(unsigned* r, unsigned addr){
    asm volatile("ldmatrix.sync.aligned.m8n8.x4.shared.b16 {%0,%1,%2,%3}, [%4];"
        : "=r"(r[0]), "=r"(r[1]), "=r"(r[2]), "=r"(r[3]) : "r"(addr));
}
__device__ __forceinline__ void mma16816h(float* d, const unsigned* a, const unsigned* b){
    asm volatile(
        "mma.sync.aligned.m16n8k16.row.col.f32.f16.f16.f32 "
        "{%0,%1,%2,%3}, {%4,%5,%6,%7}, {%8,%9}, {%0,%1,%2,%3};"
        : "+f"(d[0]), "+f"(d[1]), "+f"(d[2]), "+f"(d[3])
        : "r"(a[0]), "r"(a[1]), "r"(a[2]), "r"(a[3]), "r"(b[0]), "r"(b[1]));
}
__device__ __forceinline__ void cpasync16(unsigned saddr, const void* g){
    asm volatile("cp.async.cg.shared.global [%0], [%1], 16;" :: "r"(saddr), "l"(g) : "memory");
}
__device__ __forceinline__ void cp_commit(){
    asm volatile("cp.async.commit_group;" ::: "memory");
}
template<int N>
__device__ __forceinline__ void cp_wait(){
    asm volatile("cp.async.wait_group %0;" :: "n"(N) : "memory");
}

// ---------------- id dtype detection / maps ----------------
__global__ void detect_kernel(const long long* __restrict__ x){
    if (threadIdx.x == 0 && blockIdx.x == 0){
        int ok = 1;
        #pragma unroll
        for (int i = 0; i < 16; i++){
            long long v = x[i];
            if (v < 0 || v >= VOCAB) ok = 0;
        }
        g_is64 = ok;
    }
}

__global__ void build_maps(const void* __restrict__ xraw){
    int i = blockIdx.x * blockDim.x + threadIdx.x;
    if (i < 4*64) g_bar4[i] = 0u;
    if (i >= ML) return;
    int is64 = g_is64;
    int t = i >> 5, b = i & 31;
    long long id = is64 ? ((const long long*)xraw)[b*SEQL + t]
                        : (long long)((const int*)xraw)[b*SEQL + t];
    g_map1[i] = (int)id;
}

// ---------------- fp32 -> fp16 conversions ----------------
__device__ __forceinline__ void split4h(float4 v, uint2& uh, uint2& ul){
    __half h0 = __float2half(v.x), h1 = __float2half(v.y);
    __half h2 = __float2half(v.z), h3 = __float2half(v.w);
    __half l0 = __float2half(v.x - __half2float(h0));
    __half l1 = __float2half(v.y - __half2float(h1));
    __half l2 = __float2half(v.z - __half2float(h2));
    __half l3 = __float2half(v.w - __half2float(h3));
    __half2 p0(h0, h1), p1(h2, h3), q0(l0, l1), q1(l2, l3);
    uh.x = *(unsigned*)&p0; uh.y = *(unsigned*)&p1;
    ul.x = *(unsigned*)&q0; ul.y = *(unsigned*)&q1;
}
// A rows (HDIM fp16, hi only), gathered via map.
__global__ void convA_kernel(const float* __restrict__ src, __half* __restrict__ dst,
                             const int* __restrict__ map){
    int i = blockIdx.x * blockDim.x + threadIdx.x;   // over ML*256
    int r = i >> 8, k4 = (i & 255) << 2;
    float4 v = *(const float4*)(src + (size_t)map[r]*HDIM + k4);
    __half2 p0(__float2half(v.x), __float2half(v.y));
    __half2 p1(__float2half(v.z), __float2half(v.w));
    uint2 uh; uh.x = *(unsigned*)&p0; uh.y = *(unsigned*)&p1;
    *(uint2*)(dst + (size_t)r*HDIM + k4) = uh;
}
// B: plain fp16 downcast.
__global__ void convB_kernel(const float* __restrict__ src, __half* __restrict__ dst){
    int i = blockIdx.x * blockDim.x + threadIdx.x;   // over rows*256
    int r = i >> 8, k4 = (i & 255) << 2;
    float4 v = *(const float4*)(src + (size_t)r*HDIM + k4);
    __half2 p0(__float2half(v.x), __float2half(v.y));
    __half2 p1(__float2half(v.z), __float2half(v.w));
    uint2 uh; uh.x = *(unsigned*)&p0; uh.y = *(unsigned*)&p1;
    *(uint2*)(dst + (size_t)r*HDIM + k4) = uh;
}
// initial hidden -> [hi|lo] fp16 rows (scan-exchange format)
__global__ void convH0_kernel(const float* __restrict__ hidden, __half* __restrict__ h0){
    int i = blockIdx.x * blockDim.x + threadIdx.x;   // 32*256
    int b = i >> 8, k4 = (i & 255) << 2;
    float4 v = *(const float4*)(hidden + (size_t)b*HDIM + k4);
    uint2 uh, ul; split4h(v, uh, ul);
    *(uint2*)(h0 + (size_t)b*K2 + k4)        = uh;
    *(uint2*)(h0 + (size_t)b*K2 + 1024 + k4) = ul;
}

// ---------------- fp16 NT GEMM via mma.sync (HMMA) ----------------
// C[m][n] = sum_{k<HDIM} A[bm*256+m][k] * B[bn*128+n][k], fp32 accum.
// R12-proven config: 256x128x64 tile, 512 threads = 16 warps (8m x 2n),
// warp tile 32x64, 3-stage cp.async pipeline, XOR-swizzled SMEM.
__device__ __forceinline__ unsigned sw_off(int row, int seg){
    return (unsigned)(row*128 + ((seg ^ (row & 7)) << 4));
}

extern __shared__ __align__(16) char dynsm[];
__global__ __launch_bounds__(512,1) void gemm_tc(
    const __half* __restrict__ A, const __half* __restrict__ B,
    float* __restrict__ C, int ldc)
{
    const int tid = threadIdx.x, wid = tid >> 5, lane = tid & 31;
    const int bn = blockIdx.x, bm = blockIdx.y;
    const unsigned sbase = smem_u32(dynsm);

    const __half* Abase = A + (size_t)(bm*256)*HDIM;
    const __half* Bbase = B + (size_t)(bn*128)*HDIM;

    auto issue_stage = [&](int c, int s){
        const unsigned so = sbase + (unsigned)s*STAGE_BYTES;
        const int kk = c*BK;
        #pragma unroll
        for (int i = 0; i < 6; i++){
            int idx = tid + i*512;               // 0..3071
            int row = idx >> 3, seg = idx & 7;
            if (row < 256){
                cpasync16(so + sw_off(row, seg),
                          Abase + (size_t)row*HDIM + kk + seg*8);
            } else {
                int r = row - 256;
                cpasync16(so + 32768u + sw_off(r, seg),
                          Bbase + (size_t)r*HDIM + kk + seg*8);
            }
        }
        cp_commit();
    };

    const int wm = (wid >> 1)*32;
    const int wn = (wid & 1)*64;
    const int g = lane >> 3, r8 = lane & 7;

    float acc[2][8][4];
    #pragma unroll
    for (int mm = 0; mm < 2; mm++)
        #pragma unroll
        for (int nn = 0; nn < 8; nn++)
            #pragma unroll
            for (int j = 0; j < 4; j++) acc[mm][nn][j] = 0.f;

    issue_stage(0, 0);
    issue_stage(1, 1);

    int s = 0;
    for (int c = 0; c < KCH; c++){
        // Final chunk: its own group is the last committed -> wait_group 0.
        if (c == KCH-1) cp_wait<0>(); else cp_wait<1>();
        __syncthreads();
        if (c + 2 < KCH) issue_stage(c + 2, (c + 2) % NSTAGE);

        const unsigned offA = sbase + (unsigned)s*STAGE_BYTES;
        const unsigned offB = offA + 32768u;
        #pragma unroll
        for (int ks = 0; ks < 4; ks++){
            unsigned af[2][4], bf[4][4];
            #pragma unroll
            for (int mm = 0; mm < 2; mm++){
                int row = wm + mm*16 + r8 + (g & 1)*8;
                ldsm4(af[mm], offA + sw_off(row, ks*2 + (g >> 1)));
            }
            #pragma unroll
            for (int nt = 0; nt < 4; nt++){
                int row = wn + nt*16 + r8 + (g >> 1)*8;
                ldsm4(bf[nt], offB + sw_off(row, ks*2 + (g & 1)));
            }
            #pragma unroll
            for (int mm = 0; mm < 2; mm++)
                #pragma unroll
                for (int nt = 0; nt < 4; nt++){
                    mma16816h(acc[mm][2*nt],   af[mm], &bf[nt][0]);
                    mma16816h(acc[mm][2*nt+1], af[mm], &bf[nt][2]);
                }
        }
        s = (s + 1 == NSTAGE) ? 0 : s + 1;
    }

    const int erow = lane >> 2, ecol = (lane & 3)*2;
    #pragma unroll
    for (int mm = 0; mm < 2; mm++){
        #pragma unroll
        for (int nn = 0; nn < 8; nn++){
            size_t row = (size_t)(bm*256 + wm + mm*16 + erow);
            size_t col = (size_t)(bn*128 + wn + nn*8 + ecol);
            *(float2*)&C[row*ldc + col]       = make_float2(acc[mm][nn][0], acc[mm][nn][1]);
            *(float2*)&C[(row + 8)*ldc + col] = make_float2(acc[mm][nn][2], acc[mm][nn][3]);
        }
    }
}

// ---------------- persistent recurrent scan (HMMA step compute) ----------------
// Chain = 32 CTAs (bg). CTA: cols cg*32..+32 (M), batches bg*8..+8 (N=8).
// W_h fp16 hi/lo frags in REGISTERS. Internal h exchange keeps FULL [hi|lo]
// precision (g_hx) so recurrence error does not accumulate; the logits-A
// buffer (g_a1) additionally gets a hi-only row. nanosleep poll (proven).
__global__ __launch_bounds__(256,1) void scan_kernel(
    const __half* __restrict__ h0, const float* __restrict__ W_h,
    const float* __restrict__ pre, float* __restrict__ hout,
    __half* __restrict__ hx, __half* __restrict__ a1)
{
    __shared__ float red[8*32*8];          // [warp][m 0..31][n 0..7]
    const int tid = threadIdx.x, wid = tid >> 5, lane = tid & 31;
    const int bg = blockIdx.x >> 5, cg = blockIdx.x & 31;
    unsigned* bar = &g_bar4[bg*64];
    const int g = lane >> 3, r8 = lane & 7;
    __half* hsm = (__half*)dynsm;          // [32 rows][1032 halfs]

    // ---- init: W_h fp16 hi/lo frags (two passes over one 32-row region) ----
    unsigned wfh[2][8][4], wfl[2][8][4];
    #pragma unroll
    for (int pass = 0; pass < 2; pass++){
        for (int i = 0; i < 32; i++){
            int gi = tid + i*256;                 // float4 id, 0..8191
            int row = gi >> 8, c4 = (gi & 255) << 2;
            float4 v = *(const float4*)(W_h + (size_t)(cg*32 + row)*HDIM + c4);
            uint2 uh, ul; split4h(v, uh, ul);
            *(uint2*)((char*)hsm + row*WROWB + c4*2) = (pass == 0) ? uh : ul;
        }
        __syncthreads();
        #pragma unroll
        for (int mm = 0; mm < 2; mm++)
            #pragma unroll
            for (int kt = 0; kt < 8; kt++){
                int row = mm*16 + r8 + (g & 1)*8;
                unsigned addr = smem_u32((char*)hsm + row*WROWB
                                + wid*256 + kt*32 + (g >> 1)*16);
                if (pass == 0) ldsm4(wfh[mm][kt], addr);
                else           ldsm4(wfl[mm][kt], addr);
            }
        __syncthreads();
    }

    const int m_ = tid & 31, n_ = tid >> 5;   // reduce role: (out col, batch)
    const int gb = bg*8 + n_;
    const int oc = cg*32 + m_;

    for (int t = 0; t < SEQL; t++){
        const float preval = pre[((size_t)t*BATCH + gb)*HDIM + oc];

        // load h_{t-1} [hi|lo] rows into SMEM: hi -> rows 0-7, lo -> rows 8-15
        const __half* hbase; size_t rstride;
        if (t == 0){ hbase = h0 + (size_t)bg*8*K2; rstride = K2; }
        else { hbase = hx + ((size_t)(bg*8)*SEQL + (t-1))*K2; rstride = (size_t)SEQL*K2; }
        #pragma unroll
        for (int i = 0; i < 8; i++){
            int s = tid + i*256;                  // 16B seg id 0..2047
            int j = s >> 8;                       // batch row 0..7
            int kk = (s & 255) << 3;              // half offset 0..2040
            uint4 v = *(const uint4*)(hbase + (size_t)j*rstride + kk);
            int drow = (kk < 1024) ? j : j + 8;
            *(uint4*)((char*)hsm + drow*WROWB + (kk & 1023)*2) = v;
        }
        __syncthreads();

        float c0[4] = {0,0,0,0}, c1[4] = {0,0,0,0};
        #pragma unroll
        for (int kt = 0; kt < 8; kt++){
            unsigned hf[4];
            int row = r8 + (g >> 1)*8;
            ldsm4(hf, smem_u32((char*)hsm + row*WROWB + wid*256 + kt*32 + (g & 1)*16));
            mma16816h(c0, wfh[0][kt], &hf[0]);    // Whi * hhi
            mma16816h(c0, wfh[0][kt], &hf[2]);    // Whi * hlo
            mma16816h(c0, wfl[0][kt], &hf[0]);    // Wlo * hhi
            mma16816h(c1, wfh[1][kt], &hf[0]);
            mma16816h(c1, wfh[1][kt], &hf[2]);
            mma16816h(c1, wfl[1][kt], &hf[0]);
        }

        {
            int row = lane >> 2, col = (lane & 3)*2;
            float* rw = red + wid*256;
            rw[(row     )*8 + col] = c0[0]; rw[(row     )*8 + col+1] = c0[1];
            rw[(row +  8)*8 + col] = c0[2]; rw[(row +  8)*8 + col+1] = c0[3];
            rw[(row + 16)*8 + col] = c1[0]; rw[(row + 16)*8 + col+1] = c1[1];
            rw[(row + 24)*8 + col] = c1[2]; rw[(row + 24)*8 + col+1] = c1[3];
        }
        __syncthreads();

        {
            float dot = 0.f;
            #pragma unroll
            for (int w = 0; w < 8; w++) dot += red[w*256 + m_*8 + n_];
            float hval = tanhf(dot + preval);
            if (t == SEQL-1) hout[((size_t)t*BATCH + gb)*HDIM + oc] = hval;
            __half hh = __float2half(hval);
            __half hl = __float2half(hval - __half2float(hh));
            size_t xrow = ((size_t)gb*SEQL + t)*K2;
            hx[xrow + oc]        = hh;            // scan exchange: full precision
            hx[xrow + 1024 + oc] = hl;
            a1[((size_t)gb*SEQL + t)*HDIM + oc] = hh;  // logits A: hi only
        }

        if (t + 1 < SEQL){
            __syncthreads();
            if (tid == 0){
                bar_arrive_release(bar);
                const unsigned target = 32u*(unsigned)(t+1);
                if (ld_acquire_gpu(bar) < target){
                    while (ld_acquire_gpu(bar) < target) __nanosleep(64);
                }
            }
            __syncthreads();
        }
    }
}

__global__ void copy_hidden(float* __restrict__ dst){
    int i = blockIdx.x * blockDim.x + threadIdx.x;
    dst[i] = g_hout[(size_t)(511*32)*HDIM + i];
}

extern "C" void kernel_launch(void* const* d_in, const int* in_sizes, int n_in,
                              void* d_out, int out_size) {
    const void*  x      = d_in[0];
    const float* hidden = (const float*)d_in[1];
    const float* emb    = (const float*)d_in[2];
    const float* W_h    = (const float*)d_in[3];
    const float* W_e    = (const float*)d_in[4];
    const float* W_o    = (const float*)d_in[5];
    float* out = (float*)d_out;

    float *pre, *hout; int *map1; __half *hx, *a1, *bo, *be, *h0;
    cudaGetSymbolAddress((void**)&pre,  g_pre);
    cudaGetSymbolAddress((void**)&hout, g_hout);
    cudaGetSymbolAddress((void**)&map1, g_map1);
    cudaGetSymbolAddress((void**)&hx,   g_hx);
    cudaGetSymbolAddress((void**)&a1,   g_a1);
    cudaGetSymbolAddress((void**)&bo,   g_bo);
    cudaGetSymbolAddress((void**)&be,   g_be);
    cudaGetSymbolAddress((void**)&h0,   g_h0);

    cudaFuncSetAttribute(gemm_tc, cudaFuncAttributeMaxDynamicSharedMemorySize,
                         NSTAGE*STAGE_BYTES);
    cudaFuncSetAttribute(scan_kernel, cudaFuncAttributeMaxDynamicSharedMemorySize,
                         SCAN_SMEM);

    detect_kernel<<<1, 32>>>((const long long*)x);
    build_maps<<<64, 256>>>(x);

    // Phase 1: pre = emb[x] @ W_e^T via fp16 HMMA (K=1024, hi-only)
    convB_kernel<<<HDIM, 256>>>(W_e, be);
    convA_kernel<<<ML, 256>>>(emb, a1, map1);
    gemm_tc<<<dim3(8, 64), 512, NSTAGE*STAGE_BYTES>>>(a1, be, pre, HDIM);

    // independent preps before the scan
    convB_kernel<<<VOCAB, 256>>>(W_o, bo);
    convH0_kernel<<<32, 256>>>(hidden, h0);

    // Phase 2: persistent HMMA scan; [hi|lo] exchange + hi-only logits-A
    scan_kernel<<<128, 256, SCAN_SMEM>>>(h0, W_h, pre, hout, hx, a1);

    // Phase 3: logits = outputs @ W_o^T via fp16 HMMA (K=1024)
    gemm_tc<<<dim3(64, 64), 512, NSTAGE*STAGE_BYTES>>>(a1, bo, out, VOCAB);

    if (out_size >= LOGITS_ELEMS + BATCH*HDIM)
        copy_hidden<<<32, 1024>>>(out + LOGITS_ELEMS);
}

// round 17
// speedup vs baseline: 1.4485x; 1.4485x over previous
#include <cuda_runtime.h>
#include <cuda_bf16.h>
#include <cuda_fp16.h>
#include <cstdint>

typedef unsigned long long u64;

#define SEQL   512
#define BATCH  32
#define HDIM   1024
#define VOCAB  8192
#define ML     (BATCH*SEQL)              /* 16384 */
#define LOGITS_ELEMS 134217728           /* 32*512*8192 */
#define K2     2048                      /* A rows: [Ah|Al]; GEMM reads hi only */
#define BK     64
#define KCH    16                        /* GEMM K = 1024 (hi half only) */
#define STAGE_BYTES 49152                /* (256+128)*64*2 */
#define NSTAGE 3
#define WROWB   2064                     /* bytes per scan smem row (1032 halfs) */
#define SCAN_SMEM 66048                  /* 32 rows * 2064 B */

// ---------------- scratch (cudaMalloc forbidden) ----------------
__device__ float g_pre[ML*HDIM];                 // 64 MB, [t][b][h]
__device__ float g_hout[ML*HDIM];                // 64 MB (only t=511 used)
__device__ __half g_a2[(size_t)ML*K2];           // 64 MB: fp16 [Ah|Al] rows
__device__ __half g_bo[(size_t)VOCAB*HDIM];      // 16 MB: fp16 W_o (hi only)
__device__ __half g_be[(size_t)HDIM*HDIM];       //  2 MB: fp16 W_e (hi only)
__device__ __half g_h0[BATCH*K2];                // 128 KB: initial hidden [hi|lo]
__device__ int   g_map1[ML];             // row m=t*32+b -> embedding id
__device__ int   g_is64;
__device__ unsigned g_bar4[4*64];        // per-batch-group barrier counters

// ---------------- barrier primitives ----------------
__device__ __forceinline__ void bar_arrive_release(unsigned* p){
    asm volatile("red.release.gpu.global.add.u32 [%0], 1;" :: "l"(p) : "memory");
}
__device__ __forceinline__ unsigned ld_acquire_gpu(const unsigned* p){
    unsigned v;
    asm volatile("ld.acquire.gpu.global.u32 %0, [%1];" : "=r"(v) : "l"(p) : "memory");
    return v;
}

// ---------------- sm80-class tensor primitives (valid on plain sm_103) ----------------
__device__ __forceinline__ unsigned smem_u32(const void* p){
    unsigned a;
    asm("{ .reg .u64 t; cvta.to.shared.u64 t, %1; cvt.u32.u64 %0, t; }" : "=r"(a) : "l"(p));
    return a;
}
__device__ __forceinline__ void ldsm4(unsigned* r, unsigned addr){
    asm volatile("ldmatrix.sync.aligned.m8n8.x4.shared.b16 {%0,%1,%2,%3}, [%4];"
        : "=r"(r[0]), "=r"(r[1]), "=r"(r[2]), "=r"(r[3]) : "r"(addr));
}
__device__ __forceinline__ void mma16816h(float* d, const unsigned* a, const unsigned* b){
    asm volatile(
        "mma.sync.aligned.m16n8k16.row.col.f32.f16.f16.f32 "
        "{%0,%1,%2,%3}, {%4,%5,%6,%7}, {%8,%9}, {%0,%1,%2,%3};"
        : "+f"(d[0]), "+f"(d[1]), "+f"(d[2]), "+f"(d[3])
        : "r"(a[0]), "r"(a[1]), "r"(a[2]), "r"(a[3]), "r"(b[0]), "r"(b[1]));
}
__device__ __forceinline__ void cpasync16(unsigned saddr, const void* g){
    asm volatile("cp.async.cg.shared.global [%0], [%1], 16;" :: "r"(saddr), "l"(g) : "memory");
}
__device__ __forceinline__ void cp_commit(){
    asm volatile("cp.async.commit_group;" ::: "memory");
}
template<int N>
__device__ __forceinline__ void cp_wait(){
    asm volatile("cp.async.wait_group %0;" :: "n"(N) : "memory");
}

// ---------------- id dtype detection / maps ----------------
__global__ void detect_kernel(const long long* __restrict__ x){
    if (threadIdx.x == 0 && blockIdx.x == 0){
        int ok = 1;
        #pragma unroll
        for (int i = 0; i < 16; i++){
            long long v = x[i];
            if (v < 0 || v >= VOCAB) ok = 0;
        }
        g_is64 = ok;
    }
}

__global__ void build_maps(const void* __restrict__ xraw){
    int i = blockIdx.x * blockDim.x + threadIdx.x;
    if (i < 4*64) g_bar4[i] = 0u;
    if (i >= ML) return;
    int is64 = g_is64;
    int t = i >> 5, b = i & 31;
    long long id = is64 ? ((const long long*)xraw)[b*SEQL + t]
                        : (long long)((const int*)xraw)[b*SEQL + t];
    g_map1[i] = (int)id;
}

// ---------------- fp32 -> fp16 conversions ----------------
__device__ __forceinline__ void split4h(float4 v, uint2& uh, uint2& ul){
    __half h0 = __float2half(v.x), h1 = __float2half(v.y);
    __half h2 = __float2half(v.z), h3 = __float2half(v.w);
    __half l0 = __float2half(v.x - __half2float(h0));
    __half l1 = __float2half(v.y - __half2float(h1));
    __half l2 = __float2half(v.z - __half2float(h2));
    __half l3 = __float2half(v.w - __half2float(h3));
    __half2 p0(h0, h1), p1(h2, h3), q0(l0, l1), q1(l2, l3);
    uh.x = *(unsigned*)&p0; uh.y = *(unsigned*)&p1;
    ul.x = *(unsigned*)&q0; ul.y = *(unsigned*)&q1;
}
// A rows (K2): [Ah | Al], gathered via map (GEMM consumes hi half only).
__global__ void convA_kernel(const float* __restrict__ src, __half* __restrict__ dst,
                             const int* __restrict__ map){
    int i = blockIdx.x * blockDim.x + threadIdx.x;   // over ML*256
    int r = i >> 8, k4 = (i & 255) << 2;
    float4 v = *(const float4*)(src + (size_t)map[r]*HDIM + k4);
    uint2 uh, ul; split4h(v, uh, ul);
    size_t base = (size_t)r * K2;
    *(uint2*)(dst + base + k4)        = uh;
    *(uint2*)(dst + base + 1024 + k4) = ul;
}
// B: plain fp16 downcast.
__global__ void convB_kernel(const float* __restrict__ src, __half* __restrict__ dst){
    int i = blockIdx.x * blockDim.x + threadIdx.x;   // over rows*256
    int r = i >> 8, k4 = (i & 255) << 2;
    float4 v = *(const float4*)(src + (size_t)r*HDIM + k4);
    __half2 p0(__float2half(v.x), __float2half(v.y));
    __half2 p1(__float2half(v.z), __float2half(v.w));
    uint2 uh; uh.x = *(unsigned*)&p0; uh.y = *(unsigned*)&p1;
    *(uint2*)(dst + (size_t)r*HDIM + k4) = uh;
}
// initial hidden -> [hi|lo] fp16 rows (same format as a2 rows)
__global__ void convH0_kernel(const float* __restrict__ hidden, __half* __restrict__ h0){
    int i = blockIdx.x * blockDim.x + threadIdx.x;   // 32*256
    int b = i >> 8, k4 = (i & 255) << 2;
    float4 v = *(const float4*)(hidden + (size_t)b*HDIM + k4);
    uint2 uh, ul; split4h(v, uh, ul);
    *(uint2*)(h0 + (size_t)b*K2 + k4)        = uh;
    *(uint2*)(h0 + (size_t)b*K2 + 1024 + k4) = ul;
}

// ---------------- fp16 NT GEMM via mma.sync (HMMA) ----------------
// C[m][n] = sum_{k<1024} Ahi[bm*256+m][k] * B[bn*128+n][k], fp32 accum.
// R12-proven config (256x128x64 tile, 512 thr, 16 warps, warp tile 32x64,
// 3-stage cp.async, XOR swizzle); KCH=16 -> reads ONLY the hi half of the
// [Ah|Al] A rows (row stride K2). B chunk offset (c&15) unchanged.
__device__ __forceinline__ unsigned sw_off(int row, int seg){
    return (unsigned)(row*128 + ((seg ^ (row & 7)) << 4));
}

extern __shared__ __align__(16) char dynsm[];
__global__ __launch_bounds__(512,1) void gemm_tc(
    const __half* __restrict__ A, const __half* __restrict__ B,
    float* __restrict__ C, int ldc)
{
    const int tid = threadIdx.x, wid = tid >> 5, lane = tid & 31;
    const int bn = blockIdx.x, bm = blockIdx.y;
    const unsigned sbase = smem_u32(dynsm);

    const __half* Abase = A + (size_t)(bm*256)*K2;
    const __half* Bbase = B + (size_t)(bn*128)*HDIM;

    auto issue_stage = [&](int c, int s){
        const unsigned so = sbase + (unsigned)s*STAGE_BYTES;
        const int ak = c*BK;
        const int bk = (c & 15)*BK;
        #pragma unroll
        for (int i = 0; i < 6; i++){
            int idx = tid + i*512;               // 0..3071
            int row = idx >> 3, seg = idx & 7;
            if (row < 256){
                cpasync16(so + sw_off(row, seg),
                          Abase + (size_t)row*K2 + ak + seg*8);
            } else {
                int r = row - 256;
                cpasync16(so + 32768u + sw_off(r, seg),
                          Bbase + (size_t)r*HDIM + bk + seg*8);
            }
        }
        cp_commit();
    };

    const int wm = (wid >> 1)*32;
    const int wn = (wid & 1)*64;
    const int g = lane >> 3, r8 = lane & 7;

    float acc[2][8][4];
    #pragma unroll
    for (int mm = 0; mm < 2; mm++)
        #pragma unroll
        for (int nn = 0; nn < 8; nn++)
            #pragma unroll
            for (int j = 0; j < 4; j++) acc[mm][nn][j] = 0.f;

    issue_stage(0, 0);
    issue_stage(1, 1);

    int s = 0;
    for (int c = 0; c < KCH; c++){
        // Final chunk: its own group is the last committed -> wait_group 0.
        if (c == KCH-1) cp_wait<0>(); else cp_wait<1>();
        __syncthreads();
        if (c + 2 < KCH) issue_stage(c + 2, (c + 2) % NSTAGE);

        const unsigned offA = sbase + (unsigned)s*STAGE_BYTES;
        const unsigned offB = offA + 32768u;
        #pragma unroll
        for (int ks = 0; ks < 4; ks++){
            unsigned af[2][4], bf[4][4];
            #pragma unroll
            for (int mm = 0; mm < 2; mm++){
                int row = wm + mm*16 + r8 + (g & 1)*8;
                ldsm4(af[mm], offA + sw_off(row, ks*2 + (g >> 1)));
            }
            #pragma unroll
            for (int nt = 0; nt < 4; nt++){
                int row = wn + nt*16 + r8 + (g >> 1)*8;
                ldsm4(bf[nt], offB + sw_off(row, ks*2 + (g & 1)));
            }
            #pragma unroll
            for (int mm = 0; mm < 2; mm++)
                #pragma unroll
                for (int nt = 0; nt < 4; nt++){
                    mma16816h(acc[mm][2*nt],   af[mm], &bf[nt][0]);
                    mma16816h(acc[mm][2*nt+1], af[mm], &bf[nt][2]);
                }
        }
        s = (s + 1 == NSTAGE) ? 0 : s + 1;
    }

    const int erow = lane >> 2, ecol = (lane & 3)*2;
    #pragma unroll
    for (int mm = 0; mm < 2; mm++){
        #pragma unroll
        for (int nn = 0; nn < 8; nn++){
            size_t row = (size_t)(bm*256 + wm + mm*16 + erow);
            size_t col = (size_t)(bn*128 + wn + nn*8 + ecol);
            *(float2*)&C[row*ldc + col]       = make_float2(acc[mm][nn][0], acc[mm][nn][1]);
            *(float2*)&C[(row + 8)*ldc + col] = make_float2(acc[mm][nn][2], acc[mm][nn][3]);
        }
    }
}

// ---------------- persistent recurrent scan (HMMA step compute) ----------------
// EXACT R12 champion structure (2 stores/thread/step into ONE buffer).
// Chain = 32 CTAs (bg). CTA: cols cg*32..+32 (M), batches bg*8..+8 (N=8).
// W_h fp16 hi/lo frags in REGISTERS. h exchanged as a2 [hi|lo] rows.
__global__ __launch_bounds__(256,1) void scan_kernel(
    const __half* __restrict__ h0, const float* __restrict__ W_h,
    const float* __restrict__ pre, float* __restrict__ hout,
    __half* __restrict__ a2)
{
    __shared__ float red[8*32*8];          // [warp][m 0..31][n 0..7]
    const int tid = threadIdx.x, wid = tid >> 5, lane = tid & 31;
    const int bg = blockIdx.x >> 5, cg = blockIdx.x & 31;
    unsigned* bar = &g_bar4[bg*64];
    const int g = lane >> 3, r8 = lane & 7;
    __half* hsm = (__half*)dynsm;          // [32 rows][1032 halfs]

    // ---- init: W_h fp16 hi/lo frags (two passes over one 32-row region) ----
    unsigned wfh[2][8][4], wfl[2][8][4];
    #pragma unroll
    for (int pass = 0; pass < 2; pass++){
        for (int i = 0; i < 32; i++){
            int gi = tid + i*256;                 // float4 id, 0..8191
            int row = gi >> 8, c4 = (gi & 255) << 2;
            float4 v = *(const float4*)(W_h + (size_t)(cg*32 + row)*HDIM + c4);
            uint2 uh, ul; split4h(v, uh, ul);
            *(uint2*)((char*)hsm + row*WROWB + c4*2) = (pass == 0) ? uh : ul;
        }
        __syncthreads();
        #pragma unroll
        for (int mm = 0; mm < 2; mm++)
            #pragma unroll
            for (int kt = 0; kt < 8; kt++){
                int row = mm*16 + r8 + (g & 1)*8;
                unsigned addr = smem_u32((char*)hsm + row*WROWB
                                + wid*256 + kt*32 + (g >> 1)*16);
                if (pass == 0) ldsm4(wfh[mm][kt], addr);
                else           ldsm4(wfl[mm][kt], addr);
            }
        __syncthreads();
    }

    const int m_ = tid & 31, n_ = tid >> 5;   // reduce role: (out col, batch)
    const int gb = bg*8 + n_;
    const int oc = cg*32 + m_;

    for (int t = 0; t < SEQL; t++){
        const float preval = pre[((size_t)t*BATCH + gb)*HDIM + oc];

        // load h_{t-1} [hi|lo] rows into SMEM: hi -> rows 0-7, lo -> rows 8-15
        const __half* hbase; size_t rstride;
        if (t == 0){ hbase = h0 + (size_t)bg*8*K2; rstride = K2; }
        else { hbase = a2 + ((size_t)(bg*8)*SEQL + (t-1))*K2; rstride = (size_t)SEQL*K2; }
        #pragma unroll
        for (int i = 0; i < 8; i++){
            int s = tid + i*256;                  // 16B seg id 0..2047
            int j = s >> 8;                       // batch row 0..7
            int kk = (s & 255) << 3;              // half offset 0..2040
            uint4 v = *(const uint4*)(hbase + (size_t)j*rstride + kk);
            int drow = (kk < 1024) ? j : j + 8;
            *(uint4*)((char*)hsm + drow*WROWB + (kk & 1023)*2) = v;
        }
        __syncthreads();

        float c0[4] = {0,0,0,0}, c1[4] = {0,0,0,0};
        #pragma unroll
        for (int kt = 0; kt < 8; kt++){
            unsigned hf[4];
            int row = r8 + (g >> 1)*8;
            ldsm4(hf, smem_u32((char*)hsm + row*WROWB + wid*256 + kt*32 + (g & 1)*16));
            mma16816h(c0, wfh[0][kt], &hf[0]);    // Whi * hhi
            mma16816h(c0, wfh[0][kt], &hf[2]);    // Whi * hlo
            mma16816h(c0, wfl[0][kt], &hf[0]);    // Wlo * hhi
            mma16816h(c1, wfh[1][kt], &hf[0]);
            mma16816h(c1, wfh[1][kt], &hf[2]);
            mma16816h(c1, wfl[1][kt], &hf[0]);
        }

        {
            int row = lane >> 2, col = (lane & 3)*2;
            float* rw = red + wid*256;
            rw[(row     )*8 + col] = c0[0]; rw[(row     )*8 + col+1] = c0[1];
            rw[(row +  8)*8 + col] = c0[2]; rw[(row +  8)*8 + col+1] = c0[3];
            rw[(row + 16)*8 + col] = c1[0]; rw[(row + 16)*8 + col+1] = c1[1];
            rw[(row + 24)*8 + col] = c1[2]; rw[(row + 24)*8 + col+1] = c1[3];
        }
        __syncthreads();

        {
            float dot = 0.f;
            #pragma unroll
            for (int w = 0; w < 8; w++) dot += red[w*256 + m_*8 + n_];
            float hval = tanhf(dot + preval);
            if (t == SEQL-1) hout[((size_t)t*BATCH + gb)*HDIM + oc] = hval;
            __half hh = __float2half(hval);
            __half hl = __float2half(hval - __half2float(hh));
            size_t arow = ((size_t)gb*SEQL + t)*K2;
            a2[arow + oc]        = hh;
            a2[arow + 1024 + oc] = hl;
        }

        if (t + 1 < SEQL){
            __syncthreads();
            if (tid == 0){
                bar_arrive_release(bar);
                const unsigned target = 32u*(unsigned)(t+1);
                if (ld_acquire_gpu(bar) < target){
                    while (ld_acquire_gpu(bar) < target) __nanosleep(64);
                }
            }
            __syncthreads();
        }
    }
}

__global__ void copy_hidden(float* __restrict__ dst){
    int i = blockIdx.x * blockDim.x + threadIdx.x;
    dst[i] = g_hout[(size_t)(511*32)*HDIM + i];
}

extern "C" void kernel_launch(void* const* d_in, const int* in_sizes, int n_in,
                              void* d_out, int out_size) {
    const void*  x      = d_in[0];
    const float* hidden = (const float*)d_in[1];
    const float* emb    = (const float*)d_in[2];
    const float* W_h    = (const float*)d_in[3];
    const float* W_e    = (const float*)d_in[4];
    const float* W_o    = (const float*)d_in[5];
    float* out = (float*)d_out;

    float *pre, *hout; int *map1; __half *a2, *bo, *be, *h0;
    cudaGetSymbolAddress((void**)&pre,  g_pre);
    cudaGetSymbolAddress((void**)&hout, g_hout);
    cudaGetSymbolAddress((void**)&map1, g_map1);
    cudaGetSymbolAddress((void**)&a2,   g_a2);
    cudaGetSymbolAddress((void**)&bo,   g_bo);
    cudaGetSymbolAddress((void**)&be,   g_be);
    cudaGetSymbolAddress((void**)&h0,   g_h0);

    cudaFuncSetAttribute(gemm_tc, cudaFuncAttributeMaxDynamicSharedMemorySize,
                         NSTAGE*STAGE_BYTES);
    cudaFuncSetAttribute(scan_kernel, cudaFuncAttributeMaxDynamicSharedMemorySize,
                         SCAN_SMEM);

    detect_kernel<<<1, 32>>>((const long long*)x);
    build_maps<<<64, 256>>>(x);

    // Phase 1: pre = emb[x] @ W_e^T via fp16 HMMA (hi half of [Ah|Al], K=1024)
    convB_kernel<<<HDIM, 256>>>(W_e, be);
    convA_kernel<<<ML, 256>>>(emb, a2, map1);
    gemm_tc<<<dim3(8, 64), 512, NSTAGE*STAGE_BYTES>>>(a2, be, pre, HDIM);

    // independent preps before the scan
    convB_kernel<<<VOCAB, 256>>>(W_o, bo);
    convH0_kernel<<<32, 256>>>(hidden, h0);

    // Phase 2: persistent HMMA scan (EXACT R12 structure; writes a2 [hi|lo])
    scan_kernel<<<128, 256, SCAN_SMEM>>>(h0, W_h, pre, hout, a2);

    // Phase 3: logits = outputs @ W_o^T via fp16 HMMA (hi half only, K=1024)
    gemm_tc<<<dim3(64, 64), 512, NSTAGE*STAGE_BYTES>>>(a2, bo, out, VOCAB);

    if (out_size >= LOGITS_ELEMS + BATCH*HDIM)
        copy_hidden<<<32, 1024>>>(out + LOGITS_ELEMS);
}